// round 1
// baseline (speedup 1.0000x reference)
#include <cuda_runtime.h>
#include <cuda_bf16.h>

#ifndef D
#define D 128
#endif

__global__ __launch_bounds__(256) void sgns_kernel(
    const int*   __restrict__ x,        // [BS, 1, 3] int32
    const float* __restrict__ tgt_base, // [VOCAB, 128]
    const float* __restrict__ tgt_a,    // [SIDE, 128]
    const float* __restrict__ tgt_b,    // [SIDE, 128]
    const float* __restrict__ ctx_base, // [VOCAB, 128]
    const float* __restrict__ ctx_a,    // [SIDE, 128]
    const float* __restrict__ ctx_b,    // [SIDE, 128]
    const float* __restrict__ tgt_w,    // [3,1]
    const float* __restrict__ ctx_w,    // [3,1]
    float*       __restrict__ out,      // [BS]
    int bs)
{
    const int warp = (blockIdx.x * blockDim.x + threadIdx.x) >> 5;
    const int lane = threadIdx.x & 31;
    if (warp >= bs) return;

    // softmax(tgt_w) — 3 elements, computed redundantly per thread (cheap, L1-resident)
    float tw0 = __ldg(&tgt_w[0]), tw1 = __ldg(&tgt_w[1]), tw2 = __ldg(&tgt_w[2]);
    float tm  = fmaxf(tw0, fmaxf(tw1, tw2));
    float te0 = expf(tw0 - tm), te1 = expf(tw1 - tm), te2 = expf(tw2 - tm);
    float tinv = 1.0f / (te0 + te1 + te2);
    float w0 = te0 * tinv, w1 = te1 * tinv, w2 = te2 * tinv;

    float cw0 = __ldg(&ctx_w[0]), cw1 = __ldg(&ctx_w[1]), cw2 = __ldg(&ctx_w[2]);
    float cm  = fmaxf(cw0, fmaxf(cw1, cw2));
    float ce0 = expf(cw0 - cm), ce1 = expf(cw1 - cm), ce2 = expf(cw2 - cm);
    float cinv = 1.0f / (ce0 + ce1 + ce2);
    float v0 = ce0 * cinv, v1 = ce1 * cinv, v2 = ce2 * cinv;

    // indices (same for tgt and ctx paths)
    const int i0 = __ldg(&x[warp * 3 + 0]);
    const int i1 = __ldg(&x[warp * 3 + 1]);
    const int i2 = __ldg(&x[warp * 3 + 2]);

    // each lane owns 4 contiguous floats of the 128-dim row
    const float4 tb = __ldg((const float4*)(tgt_base + (size_t)i0 * D) + lane);
    const float4 ta = __ldg((const float4*)(tgt_a    + (size_t)i1 * D) + lane);
    const float4 tc = __ldg((const float4*)(tgt_b    + (size_t)i2 * D) + lane);
    const float4 cb = __ldg((const float4*)(ctx_base + (size_t)i0 * D) + lane);
    const float4 ca = __ldg((const float4*)(ctx_a    + (size_t)i1 * D) + lane);
    const float4 cc = __ldg((const float4*)(ctx_b    + (size_t)i2 * D) + lane);

    float tx0 = w0 * tb.x + w1 * ta.x + w2 * tc.x;
    float tx1 = w0 * tb.y + w1 * ta.y + w2 * tc.y;
    float tx2 = w0 * tb.z + w1 * ta.z + w2 * tc.z;
    float tx3 = w0 * tb.w + w1 * ta.w + w2 * tc.w;

    float cx0 = v0 * cb.x + v1 * ca.x + v2 * cc.x;
    float cx1 = v0 * cb.y + v1 * ca.y + v2 * cc.y;
    float cx2 = v0 * cb.z + v1 * ca.z + v2 * cc.z;
    float cx3 = v0 * cb.w + v1 * ca.w + v2 * cc.w;

    float p = tx0 * cx0 + tx1 * cx1 + tx2 * cx2 + tx3 * cx3;

    // warp reduction
    #pragma unroll
    for (int off = 16; off > 0; off >>= 1)
        p += __shfl_xor_sync(0xFFFFFFFFu, p, off);

    if (lane == 0)
        out[warp] = 1.0f / (1.0f + expf(-p));
}

extern "C" void kernel_launch(void* const* d_in, const int* in_sizes, int n_in,
                              void* d_out, int out_size)
{
    const int*   x        = (const int*)  d_in[0];
    const float* tgt_base = (const float*)d_in[1];
    const float* tgt_a    = (const float*)d_in[2];
    const float* tgt_b    = (const float*)d_in[3];
    const float* ctx_base = (const float*)d_in[4];
    const float* ctx_a    = (const float*)d_in[5];
    const float* ctx_b    = (const float*)d_in[6];
    const float* tgt_w    = (const float*)d_in[7];
    const float* ctx_w    = (const float*)d_in[8];
    float* out = (float*)d_out;

    const int bs = in_sizes[0] / 3;        // x has BS*1*3 elements
    const int threads = 256;               // 8 warps per block
    const int warps_per_block = threads / 32;
    const int blocks = (bs + warps_per_block - 1) / warps_per_block;

    sgns_kernel<<<blocks, threads>>>(x, tgt_base, tgt_a, tgt_b,
                                     ctx_base, ctx_a, ctx_b,
                                     tgt_w, ctx_w, out, bs);
}

// round 2
// speedup vs baseline: 1.2362x; 1.2362x over previous
#include <cuda_runtime.h>
#include <cuda_bf16.h>

#ifndef D
#define D 128
#endif

__global__ __launch_bounds__(256) void sgns_kernel2(
    const int*   __restrict__ x,        // [BS, 1, 3] int32
    const float* __restrict__ tgt_base, // [VOCAB, 128]
    const float* __restrict__ tgt_a,    // [SIDE, 128]
    const float* __restrict__ tgt_b,    // [SIDE, 128]
    const float* __restrict__ ctx_base, // [VOCAB, 128]
    const float* __restrict__ ctx_a,    // [SIDE, 128]
    const float* __restrict__ ctx_b,    // [SIDE, 128]
    const float* __restrict__ tgt_w,    // [3,1]
    const float* __restrict__ ctx_w,    // [3,1]
    float*       __restrict__ out,      // [BS]
    int bs)
{
    const int warp = (blockIdx.x * blockDim.x + threadIdx.x) >> 5;
    const int lane = threadIdx.x & 31;
    const int r0 = warp * 2;
    const int r1 = r0 + 1;
    if (r0 >= bs) return;
    const bool has_r1 = (r1 < bs);

    // indices for both rows (broadcast loads, L2/L1 resident)
    const int a0 = __ldg(&x[r0 * 3 + 0]);
    const int a1 = __ldg(&x[r0 * 3 + 1]);
    const int a2 = __ldg(&x[r0 * 3 + 2]);
    const int b0 = has_r1 ? __ldg(&x[r1 * 3 + 0]) : a0;
    const int b1 = has_r1 ? __ldg(&x[r1 * 3 + 1]) : a1;
    const int b2 = has_r1 ? __ldg(&x[r1 * 3 + 2]) : a2;

    // 12 independent gathers — issue all before any dependent math (MLP=12)
    const float4 t0b = __ldg((const float4*)(tgt_base + (size_t)a0 * D) + lane);
    const float4 t0a = __ldg((const float4*)(tgt_a    + (size_t)a1 * D) + lane);
    const float4 t0c = __ldg((const float4*)(tgt_b    + (size_t)a2 * D) + lane);
    const float4 c0b = __ldg((const float4*)(ctx_base + (size_t)a0 * D) + lane);
    const float4 c0a = __ldg((const float4*)(ctx_a    + (size_t)a1 * D) + lane);
    const float4 c0c = __ldg((const float4*)(ctx_b    + (size_t)a2 * D) + lane);

    const float4 t1b = __ldg((const float4*)(tgt_base + (size_t)b0 * D) + lane);
    const float4 t1a = __ldg((const float4*)(tgt_a    + (size_t)b1 * D) + lane);
    const float4 t1c = __ldg((const float4*)(tgt_b    + (size_t)b2 * D) + lane);
    const float4 c1b = __ldg((const float4*)(ctx_base + (size_t)b0 * D) + lane);
    const float4 c1a = __ldg((const float4*)(ctx_a    + (size_t)b1 * D) + lane);
    const float4 c1c = __ldg((const float4*)(ctx_b    + (size_t)b2 * D) + lane);

    // softmax(tgt_w), softmax(ctx_w) — overlaps with gather latency
    float tw0 = __ldg(&tgt_w[0]), tw1 = __ldg(&tgt_w[1]), tw2 = __ldg(&tgt_w[2]);
    float tm  = fmaxf(tw0, fmaxf(tw1, tw2));
    float te0 = expf(tw0 - tm), te1 = expf(tw1 - tm), te2 = expf(tw2 - tm);
    float tinv = 1.0f / (te0 + te1 + te2);
    float w0 = te0 * tinv, w1 = te1 * tinv, w2 = te2 * tinv;

    float cw0 = __ldg(&ctx_w[0]), cw1 = __ldg(&ctx_w[1]), cw2 = __ldg(&ctx_w[2]);
    float cm  = fmaxf(cw0, fmaxf(cw1, cw2));
    float ce0 = expf(cw0 - cm), ce1 = expf(cw1 - cm), ce2 = expf(cw2 - cm);
    float cinv = 1.0f / (ce0 + ce1 + ce2);
    float v0 = ce0 * cinv, v1 = ce1 * cinv, v2 = ce2 * cinv;

    // row 0 dot contribution
    float tx, cx, p0, p1;
    tx = w0 * t0b.x + w1 * t0a.x + w2 * t0c.x;
    cx = v0 * c0b.x + v1 * c0a.x + v2 * c0c.x;
    p0 = tx * cx;
    tx = w0 * t0b.y + w1 * t0a.y + w2 * t0c.y;
    cx = v0 * c0b.y + v1 * c0a.y + v2 * c0c.y;
    p0 += tx * cx;
    tx = w0 * t0b.z + w1 * t0a.z + w2 * t0c.z;
    cx = v0 * c0b.z + v1 * c0a.z + v2 * c0c.z;
    p0 += tx * cx;
    tx = w0 * t0b.w + w1 * t0a.w + w2 * t0c.w;
    cx = v0 * c0b.w + v1 * c0a.w + v2 * c0c.w;
    p0 += tx * cx;

    // row 1 dot contribution
    tx = w0 * t1b.x + w1 * t1a.x + w2 * t1c.x;
    cx = v0 * c1b.x + v1 * c1a.x + v2 * c1c.x;
    p1 = tx * cx;
    tx = w0 * t1b.y + w1 * t1a.y + w2 * t1c.y;
    cx = v0 * c1b.y + v1 * c1a.y + v2 * c1c.y;
    p1 += tx * cx;
    tx = w0 * t1b.z + w1 * t1a.z + w2 * t1c.z;
    cx = v0 * c1b.z + v1 * c1a.z + v2 * c1c.z;
    p1 += tx * cx;
    tx = w0 * t1b.w + w1 * t1a.w + w2 * t1c.w;
    cx = v0 * c1b.w + v1 * c1a.w + v2 * c1c.w;
    p1 += tx * cx;

    // warp reduction — the two chains interleave/pipeline
    #pragma unroll
    for (int off = 16; off > 0; off >>= 1) {
        p0 += __shfl_xor_sync(0xFFFFFFFFu, p0, off);
        p1 += __shfl_xor_sync(0xFFFFFFFFu, p1, off);
    }

    if (lane == 0) {
        float s0 = 1.0f / (1.0f + expf(-p0));
        float s1 = 1.0f / (1.0f + expf(-p1));
        if (has_r1) {
            *(float2*)(out + r0) = make_float2(s0, s1);  // r0 even -> 8B aligned
        } else {
            out[r0] = s0;
        }
    }
}

extern "C" void kernel_launch(void* const* d_in, const int* in_sizes, int n_in,
                              void* d_out, int out_size)
{
    const int*   x        = (const int*)  d_in[0];
    const float* tgt_base = (const float*)d_in[1];
    const float* tgt_a    = (const float*)d_in[2];
    const float* tgt_b    = (const float*)d_in[3];
    const float* ctx_base = (const float*)d_in[4];
    const float* ctx_a    = (const float*)d_in[5];
    const float* ctx_b    = (const float*)d_in[6];
    const float* tgt_w    = (const float*)d_in[7];
    const float* ctx_w    = (const float*)d_in[8];
    float* out = (float*)d_out;

    const int bs = in_sizes[0] / 3;
    const int rows_per_warp = 2;
    const int threads = 256;
    const int warps_per_block = threads / 32;
    const int rows_per_block = warps_per_block * rows_per_warp;
    const int blocks = (bs + rows_per_block - 1) / rows_per_block;

    sgns_kernel2<<<blocks, threads>>>(x, tgt_base, tgt_a, tgt_b,
                                      ctx_base, ctx_a, ctx_b,
                                      tgt_w, ctx_w, out, bs);
}